// round 4
// baseline (speedup 1.0000x reference)
#include <cuda_runtime.h>
#include <cstdint>

// EGES model:
//   hidden[b,:] = softmax(W_weights[ci]) . { W_item_in[ci], W_side0[s0], mean_j W_side1[s1_j] }
//   out[b,c]    = sigmoid( hidden[b,:] . W_item_out[ctx[b,c],:] )
//
// B=16384, D=128, K=3, S1=5, C=6. One warp per row; lane l owns float4 [4l,4l+4).
// Register diet: front-batch only the 7 DRAM gathers (item + 6 ctx);
// accumulate the 5 L2-resident side1 gathers incrementally. min-blocks=6 for
// 48 warps/SM to fill the DRAM pipe.

#define D4  32
#define NS1 5
#define NC  6

__global__ __launch_bounds__(256, 6)
void eges_kernel(const int* __restrict__ central,
                 const int* __restrict__ side0,
                 const int* __restrict__ side1,
                 const int* __restrict__ ctx,
                 const float4* __restrict__ Win,
                 const float4* __restrict__ Wout,
                 const float* __restrict__ Ww,
                 const float4* __restrict__ Ws0,
                 const float4* __restrict__ Ws1,
                 float* __restrict__ out,
                 int B)
{
    const int warp = (blockIdx.x * blockDim.x + threadIdx.x) >> 5;
    const int lane = threadIdx.x & 31;
    if (warp >= B) return;
    const int b = warp;

    // ---- indices (uniform within warp; L1 broadcast) ----
    const int ci = __ldg(&central[b]);
    const int i0 = __ldg(&side0[b]);
    int cc[NC];
#pragma unroll
    for (int j = 0; j < NC; ++j) cc[j] = __ldg(&ctx[b * NC + j]);

    // ---- front-batch the DRAM gathers: item row + 6 context rows ----
    const float4 item = Win[(size_t)ci * D4 + lane];
    float4 ov[NC];
#pragma unroll
    for (int j = 0; j < NC; ++j) ov[j] = Wout[(size_t)cc[j] * D4 + lane];

    // softmax weights (L2/L1-resident, warp-uniform)
    const float w0r = __ldg(&Ww[(size_t)ci * 3 + 0]);
    const float w1r = __ldg(&Ww[(size_t)ci * 3 + 1]);
    const float w2r = __ldg(&Ww[(size_t)ci * 3 + 2]);

    // ---- L2-resident gathers: side0 + incremental side1 mean ----
    const float4 e0 = Ws0[(size_t)i0 * D4 + lane];

    float4 e1;
    {
        const int j0 = __ldg(&side1[b * NS1 + 0]);
        const int j1 = __ldg(&side1[b * NS1 + 1]);
        float4 a = Ws1[(size_t)j0 * D4 + lane];
        float4 c = Ws1[(size_t)j1 * D4 + lane];
        e1.x = a.x + c.x; e1.y = a.y + c.y; e1.z = a.z + c.z; e1.w = a.w + c.w;
        const int j2 = __ldg(&side1[b * NS1 + 2]);
        const int j3 = __ldg(&side1[b * NS1 + 3]);
        a = Ws1[(size_t)j2 * D4 + lane];
        c = Ws1[(size_t)j3 * D4 + lane];
        e1.x += a.x + c.x; e1.y += a.y + c.y; e1.z += a.z + c.z; e1.w += a.w + c.w;
        const int j4 = __ldg(&side1[b * NS1 + 4]);
        a = Ws1[(size_t)j4 * D4 + lane];
        e1.x = (e1.x + a.x) * 0.2f;
        e1.y = (e1.y + a.y) * 0.2f;
        e1.z = (e1.z + a.z) * 0.2f;
        e1.w = (e1.w + a.w) * 0.2f;
    }

    // ---- stable softmax over 3 weights ----
    const float m  = fmaxf(w0r, fmaxf(w1r, w2r));
    const float x0 = __expf(w0r - m), x1 = __expf(w1r - m), x2 = __expf(w2r - m);
    const float inv = 1.0f / (x0 + x1 + x2);
    const float w0 = x0 * inv, w1 = x1 * inv, w2 = x2 * inv;

    // ---- hidden ----
    float4 h;
    h.x = w0 * item.x + w1 * e0.x + w2 * e1.x;
    h.y = w0 * item.y + w1 * e0.y + w2 * e1.y;
    h.z = w0 * item.z + w1 * e0.z + w2 * e1.z;
    h.w = w0 * item.w + w1 * e0.w + w2 * e1.w;

    // ---- 6 dots + interleaved butterfly reductions ----
    float d0 = h.x * ov[0].x + h.y * ov[0].y + h.z * ov[0].z + h.w * ov[0].w;
    float d1 = h.x * ov[1].x + h.y * ov[1].y + h.z * ov[1].z + h.w * ov[1].w;
    float d2 = h.x * ov[2].x + h.y * ov[2].y + h.z * ov[2].z + h.w * ov[2].w;
    float d3 = h.x * ov[3].x + h.y * ov[3].y + h.z * ov[3].z + h.w * ov[3].w;
    float d4 = h.x * ov[4].x + h.y * ov[4].y + h.z * ov[4].z + h.w * ov[4].w;
    float d5 = h.x * ov[5].x + h.y * ov[5].y + h.z * ov[5].z + h.w * ov[5].w;

#pragma unroll
    for (int off = 16; off > 0; off >>= 1) {
        d0 += __shfl_xor_sync(0xFFFFFFFFu, d0, off);
        d1 += __shfl_xor_sync(0xFFFFFFFFu, d1, off);
        d2 += __shfl_xor_sync(0xFFFFFFFFu, d2, off);
        d3 += __shfl_xor_sync(0xFFFFFFFFu, d3, off);
        d4 += __shfl_xor_sync(0xFFFFFFFFu, d4, off);
        d5 += __shfl_xor_sync(0xFFFFFFFFu, d5, off);
    }

    if (lane == 0) {
        float2* o2 = (float2*)(out + (size_t)b * NC);   // 24B row stride -> 8B aligned
        float2 p;
        p.x = 1.0f / (1.0f + __expf(-d0));
        p.y = 1.0f / (1.0f + __expf(-d1));
        o2[0] = p;
        p.x = 1.0f / (1.0f + __expf(-d2));
        p.y = 1.0f / (1.0f + __expf(-d3));
        o2[1] = p;
        p.x = 1.0f / (1.0f + __expf(-d4));
        p.y = 1.0f / (1.0f + __expf(-d5));
        o2[2] = p;
    }
}

extern "C" void kernel_launch(void* const* d_in, const int* in_sizes, int n_in,
                              void* d_out, int out_size)
{
    const int*    central = (const int*)d_in[0];
    const int*    side0   = (const int*)d_in[1];
    const int*    side1   = (const int*)d_in[2];
    const int*    ctx     = (const int*)d_in[3];
    const float4* Win     = (const float4*)d_in[4];
    const float4* Wout    = (const float4*)d_in[5];
    const float*  Ww      = (const float*)d_in[6];
    const float4* Ws0     = (const float4*)d_in[7];
    const float4* Ws1     = (const float4*)d_in[8];
    float* out = (float*)d_out;

    const int B = in_sizes[0];
    const int blocks = (B + 7) / 8;   // 8 warps/block
    eges_kernel<<<blocks, 256>>>(central, side0, side1, ctx,
                                 Win, Wout, Ww, Ws0, Ws1, out, B);
}